// round 13
// baseline (speedup 1.0000x reference)
#include <cuda_runtime.h>
#include <cuda_fp16.h>
#include <cstdint>

#define B_ 4
#define S_ 2048
#define D_ 1024
#define P_ 1024

#define BM 128
#define BN 128
#define BK 64                        // halves of k per chunk
#define NT_ 256
#define NSTAGE 3
#define BKH 72                       // A/B k-major row stride in halves (144B)
#define BTN 136                      // bt-mode B row stride in halves (272B)
#define TILE_H (BM * BKH)
#define A_TILE_B (TILE_H * 2)        // 18432
#define STAGE_BYTES (2 * A_TILE_B)   // 36864
#define SMEM_BYTES (NSTAGE * STAGE_BYTES)  // 110592 -> 2 CTAs/SM

#define NX4 ((B_ * S_ * D_) / 4)
#define NW4 ((P_ * D_) / 4)

// Scratch (static device arrays; no dynamic allocation anywhere).
__device__ __half g_Q  [(size_t)B_ * S_ * P_];
__device__ __half g_K  [(size_t)B_ * S_ * P_];
__device__ __half g_V  [(size_t)B_ * S_ * P_];
__device__ __half g_W  [(size_t)B_ * S_ * S_];   // unnormalized exp weights
__device__ float  g_inv[(size_t)B_ * S_];        // 1 / row sums
__device__ __half g_xh [(size_t)B_ * S_ * D_];
__device__ __half g_Wh [3][(size_t)P_ * D_];

__device__ __forceinline__ uint32_t smem_u32(const void* p) {
    uint32_t a;
    asm("{ .reg .u64 t; cvta.to.shared.u64 t, %1; cvt.u32.u64 %0, t; }" : "=r"(a) : "l"(p));
    return a;
}
__device__ __forceinline__ void cp16(uint32_t dst, const void* src) {
    asm volatile("cp.async.cg.shared.global [%0], [%1], 16;" :: "r"(dst), "l"(src));
}
#define CP_COMMIT() asm volatile("cp.async.commit_group;" ::: "memory")
#define CP_WAIT(n)  asm volatile("cp.async.wait_group %0;" :: "n"(n) : "memory")

#define LDSM4(r0, r1, r2, r3, a)                                                  \
    asm volatile("ldmatrix.sync.aligned.m8n8.x4.shared.b16 {%0,%1,%2,%3}, [%4];"  \
        : "=r"(r0), "=r"(r1), "=r"(r2), "=r"(r3) : "r"(a))
#define LDSM4T(r0, r1, r2, r3, a)                                                 \
    asm volatile("ldmatrix.sync.aligned.m8n8.x4.trans.shared.b16 {%0,%1,%2,%3}, [%4];" \
        : "=r"(r0), "=r"(r1), "=r"(r2), "=r"(r3) : "r"(a))

__device__ __forceinline__ void mma_f16(float* c, const uint32_t* a,
                                        uint32_t b0, uint32_t b1) {
    asm volatile(
        "mma.sync.aligned.m16n8k16.row.col.f32.f16.f16.f32 "
        "{%0,%1,%2,%3}, {%4,%5,%6,%7}, {%8,%9}, {%0,%1,%2,%3};"
        : "+f"(c[0]), "+f"(c[1]), "+f"(c[2]), "+f"(c[3])
        : "r"(a[0]), "r"(a[1]), "r"(a[2]), "r"(a[3]), "r"(b0), "r"(b1));
}

// bt=0: C[m,n] = sum_k A[m,k] * B[n,k] (B row-major [N,K])
// bt=1: C[m,n] = sum_k A[m,k] * B[k,n] (B row-major [K,N], ldmatrix.trans path)
// mode 0 (projections): z selects B0/B1/B2 -> Ch0/Ch1/Ch2 (half out);
//         z==0 output (Q) additionally scaled by ascale.
// mode 1: A += z*sA, B = B0 + z*sB, C = z-strided.
// fexp: epilogue stores exp(acc) with causal intra-tile mask, half out.
// rinv: Z mode — epilogue scales row r by rinv[z*M + r] (fp32 out).
__global__ __launch_bounds__(NT_, 2) void gemm_nt_h(
    const __half* __restrict__ A,
    const __half* __restrict__ B0, const __half* __restrict__ B1, const __half* __restrict__ B2,
    float* __restrict__ Cf, __half* __restrict__ Ch0, __half* __restrict__ Ch1, __half* __restrict__ Ch2,
    int M, int N, int K, long long sA, long long sB, long long sC,
    int mode, int causal, int klim, int out_half, int bt, float ascale,
    int fexp, const float* __restrict__ rinv)
{
    extern __shared__ char smraw[];
    const int m0 = blockIdx.y * BM;
    const int n0 = blockIdx.x * BN;
    if (causal && n0 > m0) return;

    const __half* B;
    float* Cf_ = Cf;
    __half* Ch_ = Ch0;
    float osc = 1.f;
    if (mode == 0) {
        B   = (blockIdx.z == 0) ? B0 : (blockIdx.z == 1) ? B1 : B2;
        Ch_ = (blockIdx.z == 0) ? Ch0 : (blockIdx.z == 1) ? Ch1 : Ch2;
        if (blockIdx.z == 0) osc = ascale;
    } else {
        A += (long long)blockIdx.z * sA;
        B = B0 + (long long)blockIdx.z * sB;
        if (out_half) Ch_ = Ch0 + (long long)blockIdx.z * sC;
        else          Cf_ = Cf  + (long long)blockIdx.z * sC;
    }
    const float* invb = rinv ? (rinv + (long long)blockIdx.z * M) : nullptr;

    const int kmax = klim ? min(K, m0 + BM) : K;
    const int nchunk = kmax / BK;

    const int tid = threadIdx.x;
    const int wid = tid >> 5, lane = tid & 31;
    const int g = lane >> 2, tg = lane & 3;
    const int wm = (wid >> 2) * 64;
    const int wn = (wid & 3) * 32;

    const uint32_t sbase = smem_u32(smraw);
    const __half* Abase = A + (size_t)m0 * K;

    uint32_t offA[4], offB[2];
    {
        const int rA = lane & 15;
        const int cA = (lane >> 4) * 16;
        #pragma unroll
        for (int mt = 0; mt < 4; mt++)
            offA[mt] = (uint32_t)((wm + mt * 16 + rA) * BKH) * 2u + cA;
        if (!bt) {
            const int rB = (lane & 7) + ((lane >> 4) << 3);
            const int cB = ((lane >> 3) & 1) * 16;
            #pragma unroll
            for (int gb = 0; gb < 2; gb++)
                offB[gb] = (uint32_t)A_TILE_B +
                           (uint32_t)((wn + gb * 16 + rB) * BKH) * 2u + cB;
        } else {
            const int rK = (lane & 7) + (((lane >> 3) & 1) << 3);
            const int oc = (lane >> 4) * 8;
            #pragma unroll
            for (int gb = 0; gb < 2; gb++)
                offB[gb] = (uint32_t)A_TILE_B +
                           (uint32_t)(rK * BTN + wn + gb * 16 + oc) * 2u;
        }
    }

    float acc[4][4][4];
    #pragma unroll
    for (int i = 0; i < 4; i++)
        #pragma unroll
        for (int j = 0; j < 4; j++)
            #pragma unroll
            for (int r = 0; r < 4; r++) acc[i][j][r] = 0.f;

    auto load_stage = [&](int c, int s) {
        const uint32_t ab = sbase + (uint32_t)s * STAGE_BYTES;
        const uint32_t bb = ab + A_TILE_B;
        const __half* Ag = Abase + (size_t)c * BK;
        #pragma unroll
        for (int j = 0; j < 4; j++) {
            int idx = j * NT_ + tid;
            int row = idx >> 3;
            int kc = (idx & 7) * 8;
            cp16(ab + (uint32_t)(row * BKH + kc) * 2u, Ag + (size_t)row * K + kc);
        }
        if (!bt) {
            const __half* Bg = B + (size_t)n0 * K + (size_t)c * BK;
            #pragma unroll
            for (int j = 0; j < 4; j++) {
                int idx = j * NT_ + tid;
                int row = idx >> 3;
                int kc = (idx & 7) * 8;
                cp16(bb + (uint32_t)(row * BKH + kc) * 2u, Bg + (size_t)row * K + kc);
            }
        } else {
            const __half* Bg = B + (size_t)c * BK * N + n0;
            #pragma unroll
            for (int j = 0; j < 4; j++) {
                int idx = j * NT_ + tid;
                int row = idx >> 4;
                int nc = (idx & 15) * 8;
                cp16(bb + (uint32_t)(row * BTN + nc) * 2u, Bg + (size_t)row * N + nc);
            }
        }
    };

    load_stage(0, 0);
    CP_COMMIT();
    load_stage(1, 1);
    CP_COMMIT();

    uint32_t af[2][4][4], bf[2][2][4];

    auto ldsm_step = [&](uint32_t stb, int kk, int buf) {
        const uint32_t koA = (uint32_t)kk * 32u;
        #pragma unroll
        for (int mt = 0; mt < 4; mt++)
            LDSM4(af[buf][mt][0], af[buf][mt][1], af[buf][mt][2], af[buf][mt][3],
                  stb + offA[mt] + koA);
        if (!bt) {
            #pragma unroll
            for (int gb = 0; gb < 2; gb++)
                LDSM4(bf[buf][gb][0], bf[buf][gb][1], bf[buf][gb][2], bf[buf][gb][3],
                      stb + offB[gb] + koA);
        } else {
            const uint32_t koB = (uint32_t)kk * (16u * BTN * 2u);
            #pragma unroll
            for (int gb = 0; gb < 2; gb++)
                LDSM4T(bf[buf][gb][0], bf[buf][gb][1], bf[buf][gb][2], bf[buf][gb][3],
                       stb + offB[gb] + koB);
        }
    };
    auto mma_step = [&](int buf) {
        #pragma unroll
        for (int mt = 0; mt < 4; mt++)
            #pragma unroll
            for (int nt = 0; nt < 4; nt++)
                mma_f16(acc[mt][nt], af[buf][mt],
                        bf[buf][nt >> 1][(nt & 1) * 2], bf[buf][nt >> 1][(nt & 1) * 2 + 1]);
    };

    int sc = 0;
    for (int i = 0; i < nchunk; i++) {
        CP_WAIT(1);
        __syncthreads();

        const int c2 = i + 2;
        if (c2 < nchunk) load_stage(c2, c2 % NSTAGE);
        CP_COMMIT();

        const uint32_t stb = sbase + (uint32_t)sc * STAGE_BYTES;
        ldsm_step(stb, 0, 0);
        #pragma unroll
        for (int kk = 0; kk < 4; kk++) {
            const int cur = kk & 1;
            if (kk < 3) ldsm_step(stb, kk + 1, cur ^ 1);
            mma_step(cur);
        }
        if (++sc == NSTAGE) sc = 0;
    }

    #pragma unroll
    for (int mt = 0; mt < 4; mt++) {
        const int row = m0 + wm + mt * 16 + g;
        float iv0 = 1.f, iv8 = 1.f;
        if (invb) { iv0 = invb[row]; iv8 = invb[row + 8]; }
        #pragma unroll
        for (int nt = 0; nt < 4; nt++) {
            const int col = n0 + wn + nt * 8 + tg * 2;
            if (fexp) {
                // exp + causal intra-tile mask; store unnormalized half weights
                float e0 = (col     <= row)     ? __expf(acc[mt][nt][0]) : 0.f;
                float e1 = (col + 1 <= row)     ? __expf(acc[mt][nt][1]) : 0.f;
                float e2 = (col     <= row + 8) ? __expf(acc[mt][nt][2]) : 0.f;
                float e3 = (col + 1 <= row + 8) ? __expf(acc[mt][nt][3]) : 0.f;
                *(__half2*)(Ch_ + (size_t)row * N + col) = __floats2half2_rn(e0, e1);
                *(__half2*)(Ch_ + (size_t)(row + 8) * N + col) = __floats2half2_rn(e2, e3);
            } else if (out_half) {
                *(__half2*)(Ch_ + (size_t)row * N + col) =
                    __floats2half2_rn(acc[mt][nt][0] * osc, acc[mt][nt][1] * osc);
                *(__half2*)(Ch_ + (size_t)(row + 8) * N + col) =
                    __floats2half2_rn(acc[mt][nt][2] * osc, acc[mt][nt][3] * osc);
            } else {
                *(float2*)(Cf_ + (size_t)row * N + col) =
                    make_float2(acc[mt][nt][0] * iv0, acc[mt][nt][1] * iv0);
                *(float2*)(Cf_ + (size_t)(row + 8) * N + col) =
                    make_float2(acc[mt][nt][2] * iv8, acc[mt][nt][3] * iv8);
            }
        }
    }
}

// ---------------- fp32 -> fp16 conversion, one launch ----------------
__global__ __launch_bounds__(256) void to_half_all(
    const float* __restrict__ x,  __half* __restrict__ xh,
    const float* __restrict__ w0, const float* __restrict__ w1, const float* __restrict__ w2,
    __half* __restrict__ wh)
{
    int i = blockIdx.x * 256 + threadIdx.x;
    const float* src;
    __half* dst;
    int off;
    if (i < NX4) { src = x; dst = xh; off = i; }
    else {
        int j = i - NX4;
        int w = j / NW4;
        off = j - w * NW4;
        src = (w == 0) ? w0 : (w == 1) ? w1 : w2;
        dst = wh + (size_t)w * (P_ * D_);
    }
    float4 v = ((const float4*)src)[off];
    __half2 h0 = __floats2half2_rn(v.x, v.y);
    __half2 h1 = __floats2half2_rn(v.z, v.w);
    ((uint2*)dst)[off] = make_uint2(*(uint32_t*)&h0, *(uint32_t*)&h1);
}

// ---------------- row-sum of exp weights -> inverse ----------------
__global__ __launch_bounds__(256) void row_inv(
    const __half* __restrict__ W, float* __restrict__ inv, int n)
{
    const int q = blockIdx.x;
    const __half* row = W + ((long long)blockIdx.y * n + q) * (long long)n;
    const int tid = threadIdx.x;
    const int wid = tid >> 5, lane = tid & 31;
    const int lim = ((q >> 7) + 1) << 7;   // masked region within lim is exact 0

    float sum = 0.f;
    for (int base = tid * 8; base < lim; base += 2048) {
        uint4 u = *(const uint4*)(row + base);   // 8 halves
        __half2 a = *(__half2*)&u.x, b = *(__half2*)&u.y;
        __half2 c = *(__half2*)&u.z, d = *(__half2*)&u.w;
        float2 fa = __half22float2(a), fb = __half22float2(b);
        float2 fc = __half22float2(c), fd = __half22float2(d);
        sum += (fa.x + fa.y) + (fb.x + fb.y) + (fc.x + fc.y) + (fd.x + fd.y);
    }
    __shared__ float red[8];
    #pragma unroll
    for (int o = 16; o > 0; o >>= 1) sum += __shfl_xor_sync(0xffffffffu, sum, o);
    if (lane == 0) red[wid] = sum;
    __syncthreads();
    if (tid == 0) {
        float s = red[0];
        #pragma unroll
        for (int w = 1; w < 8; w++) s += red[w];
        inv[(long long)blockIdx.y * n + q] = 1.f / s;
    }
}

// ---------------- launcher (single stream, 4 launches) ----------------
extern "C" void kernel_launch(void* const* d_in, const int* in_sizes, int n_in,
                              void* d_out, int out_size)
{
    const float* x  = (const float*)d_in[0];
    const float* Wq = (const float*)d_in[1];
    const float* Wk = (const float*)d_in[2];
    const float* Wv = (const float*)d_in[3];
    float* out = (float*)d_out;

    __half *Q, *K, *V, *Wgt, *xh, *Wh;
    float *inv;
    cudaGetSymbolAddress((void**)&Q,   g_Q);
    cudaGetSymbolAddress((void**)&K,   g_K);
    cudaGetSymbolAddress((void**)&V,   g_V);
    cudaGetSymbolAddress((void**)&Wgt, g_W);
    cudaGetSymbolAddress((void**)&inv, g_inv);
    cudaGetSymbolAddress((void**)&xh,  g_xh);
    cudaGetSymbolAddress((void**)&Wh,  g_Wh);
    __half* Wqh = Wh;
    __half* Wkh = Wh + (size_t)P_ * D_;
    __half* Wvh = Wh + 2 * (size_t)P_ * D_;

    cudaFuncSetAttribute(gemm_nt_h, cudaFuncAttributeMaxDynamicSharedMemorySize, SMEM_BYTES);

    const int tot4 = NX4 + 3 * NW4;
    to_half_all<<<(tot4 + 255) / 256, 256>>>(x, xh, Wq, Wk, Wv, Wh);

    dim3 blk(NT_);

    // merged QKV projections; Q scaled by 1/sqrt(d) at the epilogue
    dim3 gproj(P_ / BN, (B_ * S_) / BM, 3);
    gemm_nt_h<<<gproj, blk, SMEM_BYTES>>>(xh, Wqh, Wkh, Wvh,
                                          nullptr, Q, K, V,
                                          B_ * S_, P_, D_, 0, 0, 0, 0, 0, 0, 1, 0,
                                          0.03125f, 0, nullptr);

    // exp-weights = exp((Q/32) @ K^T) with causal mask, half out (per batch)
    dim3 gsc(S_ / BN, S_ / BM, B_);
    gemm_nt_h<<<gsc, blk, SMEM_BYTES>>>(Q, K, nullptr, nullptr,
                                        nullptr, Wgt, nullptr, nullptr,
                                        S_, S_, P_,
                                        (long long)S_ * P_, (long long)S_ * P_,
                                        (long long)S_ * S_, 1, 1, 0, 1, 0, 1.f,
                                        1, nullptr);

    // per-row inverse sums
    row_inv<<<dim3(S_, B_), 256>>>(Wgt, inv, S_);

    // Z = (expW @ V) * inv[row] per batch (bt=1 trans path), k truncated
    dim3 gz(P_ / BN, S_ / BM, B_);
    gemm_nt_h<<<gz, blk, SMEM_BYTES>>>(Wgt, V, nullptr, nullptr,
                                       out, nullptr, nullptr, nullptr,
                                       S_, P_, S_,
                                       (long long)S_ * S_, (long long)S_ * P_,
                                       (long long)S_ * P_, 1, 0, 1, 0, 1, 1.f,
                                       0, inv);
}

// round 16
// speedup vs baseline: 1.0234x; 1.0234x over previous
#include <cuda_runtime.h>
#include <cuda_fp16.h>
#include <cstdint>

#define B_ 4
#define S_ 2048
#define D_ 1024
#define P_ 1024

#define BM 128
#define BN 128
#define BK 64                        // halves of k per chunk
#define NT_ 256
#define NSTAGE 3
#define BKH 72                       // A/B k-major row stride in halves (144B)
#define BTN 136                      // bt-mode B row stride in halves (272B)
#define TILE_H (BM * BKH)
#define A_TILE_B (TILE_H * 2)        // 18432
#define STAGE_BYTES (2 * A_TILE_B)   // 36864
#define SMEM_BYTES (NSTAGE * STAGE_BYTES)  // 110592 -> 2 CTAs/SM

#define NX4 ((B_ * S_ * D_) / 4)
#define NW4 ((P_ * D_) / 4)

// Scratch (static device arrays; no dynamic allocation anywhere).
__device__ __half g_Q  [(size_t)B_ * S_ * P_];
__device__ __half g_K  [(size_t)B_ * S_ * P_];
__device__ __half g_V  [(size_t)B_ * S_ * P_];
__device__ __half g_W  [(size_t)B_ * S_ * S_];   // unnormalized exp weights
__device__ float  g_sum[(size_t)B_ * S_];        // row sums (atomic-accumulated)
__device__ __half g_xh [(size_t)B_ * S_ * D_];
__device__ __half g_Wh [3][(size_t)P_ * D_];

__device__ __forceinline__ uint32_t smem_u32(const void* p) {
    uint32_t a;
    asm("{ .reg .u64 t; cvta.to.shared.u64 t, %1; cvt.u32.u64 %0, t; }" : "=r"(a) : "l"(p));
    return a;
}
__device__ __forceinline__ void cp16(uint32_t dst, const void* src) {
    asm volatile("cp.async.cg.shared.global [%0], [%1], 16;" :: "r"(dst), "l"(src));
}
#define CP_COMMIT() asm volatile("cp.async.commit_group;" ::: "memory")
#define CP_WAIT(n)  asm volatile("cp.async.wait_group %0;" :: "n"(n) : "memory")

#define LDSM4(r0, r1, r2, r3, a)                                                  \
    asm volatile("ldmatrix.sync.aligned.m8n8.x4.shared.b16 {%0,%1,%2,%3}, [%4];"  \
        : "=r"(r0), "=r"(r1), "=r"(r2), "=r"(r3) : "r"(a))
#define LDSM4T(r0, r1, r2, r3, a)                                                 \
    asm volatile("ldmatrix.sync.aligned.m8n8.x4.trans.shared.b16 {%0,%1,%2,%3}, [%4];" \
        : "=r"(r0), "=r"(r1), "=r"(r2), "=r"(r3) : "r"(a))

__device__ __forceinline__ void mma_f16(float* c, const uint32_t* a,
                                        uint32_t b0, uint32_t b1) {
    asm volatile(
        "mma.sync.aligned.m16n8k16.row.col.f32.f16.f16.f32 "
        "{%0,%1,%2,%3}, {%4,%5,%6,%7}, {%8,%9}, {%0,%1,%2,%3};"
        : "+f"(c[0]), "+f"(c[1]), "+f"(c[2]), "+f"(c[3])
        : "r"(a[0]), "r"(a[1]), "r"(a[2]), "r"(a[3]), "r"(b0), "r"(b1));
}

// bt=0: C[m,n] = sum_k A[m,k] * B[n,k] (B row-major [N,K])
// bt=1: C[m,n] = sum_k A[m,k] * B[k,n] (B row-major [K,N], ldmatrix.trans path)
// mode 0 (projections): z selects B0/B1/B2 -> Ch0/Ch1/Ch2 (half out);
//         z==0 output (Q) additionally scaled by ascale.
// mode 1: A += z*sA, B = B0 + z*sB, C = z-strided.
// fexp: epilogue stores exp(acc) with causal intra-tile mask (half out) and
//       atomically accumulates per-row sums into rsum[z*M + row].
// rinv mode (fexp==0, out_half==0, rsum!=null): scale row r by 1/rsum[z*M+r].
__global__ __launch_bounds__(NT_, 2) void gemm_nt_h(
    const __half* __restrict__ A,
    const __half* __restrict__ B0, const __half* __restrict__ B1, const __half* __restrict__ B2,
    float* __restrict__ Cf, __half* __restrict__ Ch0, __half* __restrict__ Ch1, __half* __restrict__ Ch2,
    int M, int N, int K, long long sA, long long sB, long long sC,
    int mode, int causal, int klim, int out_half, int bt, float ascale,
    int fexp, float* __restrict__ rsum)
{
    extern __shared__ char smraw[];
    const int m0 = blockIdx.y * BM;
    const int n0 = blockIdx.x * BN;
    if (causal && n0 > m0) return;

    const __half* B;
    float* Cf_ = Cf;
    __half* Ch_ = Ch0;
    float osc = 1.f;
    if (mode == 0) {
        B   = (blockIdx.z == 0) ? B0 : (blockIdx.z == 1) ? B1 : B2;
        Ch_ = (blockIdx.z == 0) ? Ch0 : (blockIdx.z == 1) ? Ch1 : Ch2;
        if (blockIdx.z == 0) osc = ascale;
    } else {
        A += (long long)blockIdx.z * sA;
        B = B0 + (long long)blockIdx.z * sB;
        if (out_half) Ch_ = Ch0 + (long long)blockIdx.z * sC;
        else          Cf_ = Cf  + (long long)blockIdx.z * sC;
    }
    float* sums = rsum ? (rsum + (long long)blockIdx.z * M) : nullptr;

    const int kmax = klim ? min(K, m0 + BM) : K;
    const int nchunk = kmax / BK;

    const int tid = threadIdx.x;
    const int wid = tid >> 5, lane = tid & 31;
    const int g = lane >> 2, tg = lane & 3;
    const int wm = (wid >> 2) * 64;
    const int wn = (wid & 3) * 32;

    const uint32_t sbase = smem_u32(smraw);
    const __half* Abase = A + (size_t)m0 * K;

    uint32_t offA[4], offB[2];
    {
        const int rA = lane & 15;
        const int cA = (lane >> 4) * 16;
        #pragma unroll
        for (int mt = 0; mt < 4; mt++)
            offA[mt] = (uint32_t)((wm + mt * 16 + rA) * BKH) * 2u + cA;
        if (!bt) {
            const int rB = (lane & 7) + ((lane >> 4) << 3);
            const int cB = ((lane >> 3) & 1) * 16;
            #pragma unroll
            for (int gb = 0; gb < 2; gb++)
                offB[gb] = (uint32_t)A_TILE_B +
                           (uint32_t)((wn + gb * 16 + rB) * BKH) * 2u + cB;
        } else {
            const int rK = (lane & 7) + (((lane >> 3) & 1) << 3);
            const int oc = (lane >> 4) * 8;
            #pragma unroll
            for (int gb = 0; gb < 2; gb++)
                offB[gb] = (uint32_t)A_TILE_B +
                           (uint32_t)(rK * BTN + wn + gb * 16 + oc) * 2u;
        }
    }

    float acc[4][4][4];
    #pragma unroll
    for (int i = 0; i < 4; i++)
        #pragma unroll
        for (int j = 0; j < 4; j++)
            #pragma unroll
            for (int r = 0; r < 4; r++) acc[i][j][r] = 0.f;

    auto load_stage = [&](int c, int s) {
        const uint32_t ab = sbase + (uint32_t)s * STAGE_BYTES;
        const uint32_t bb = ab + A_TILE_B;
        const __half* Ag = Abase + (size_t)c * BK;
        #pragma unroll
        for (int j = 0; j < 4; j++) {
            int idx = j * NT_ + tid;
            int row = idx >> 3;
            int kc = (idx & 7) * 8;
            cp16(ab + (uint32_t)(row * BKH + kc) * 2u, Ag + (size_t)row * K + kc);
        }
        if (!bt) {
            const __half* Bg = B + (size_t)n0 * K + (size_t)c * BK;
            #pragma unroll
            for (int j = 0; j < 4; j++) {
                int idx = j * NT_ + tid;
                int row = idx >> 3;
                int kc = (idx & 7) * 8;
                cp16(bb + (uint32_t)(row * BKH + kc) * 2u, Bg + (size_t)row * K + kc);
            }
        } else {
            const __half* Bg = B + (size_t)c * BK * N + n0;
            #pragma unroll
            for (int j = 0; j < 4; j++) {
                int idx = j * NT_ + tid;
                int row = idx >> 4;
                int nc = (idx & 15) * 8;
                cp16(bb + (uint32_t)(row * BTN + nc) * 2u, Bg + (size_t)row * N + nc);
            }
        }
    };

    load_stage(0, 0);
    CP_COMMIT();
    load_stage(1, 1);
    CP_COMMIT();

    uint32_t af[2][4][4], bf[2][2][4];

    auto ldsm_step = [&](uint32_t stb, int kk, int buf) {
        const uint32_t koA = (uint32_t)kk * 32u;
        #pragma unroll
        for (int mt = 0; mt < 4; mt++)
            LDSM4(af[buf][mt][0], af[buf][mt][1], af[buf][mt][2], af[buf][mt][3],
                  stb + offA[mt] + koA);
        if (!bt) {
            #pragma unroll
            for (int gb = 0; gb < 2; gb++)
                LDSM4(bf[buf][gb][0], bf[buf][gb][1], bf[buf][gb][2], bf[buf][gb][3],
                      stb + offB[gb] + koA);
        } else {
            const uint32_t koB = (uint32_t)kk * (16u * BTN * 2u);
            #pragma unroll
            for (int gb = 0; gb < 2; gb++)
                LDSM4T(bf[buf][gb][0], bf[buf][gb][1], bf[buf][gb][2], bf[buf][gb][3],
                       stb + offB[gb] + koB);
        }
    };
    auto mma_step = [&](int buf) {
        #pragma unroll
        for (int mt = 0; mt < 4; mt++)
            #pragma unroll
            for (int nt = 0; nt < 4; nt++)
                mma_f16(acc[mt][nt], af[buf][mt],
                        bf[buf][nt >> 1][(nt & 1) * 2], bf[buf][nt >> 1][(nt & 1) * 2 + 1]);
    };

    int sc = 0;
    for (int i = 0; i < nchunk; i++) {
        CP_WAIT(1);
        __syncthreads();

        const int c2 = i + 2;
        if (c2 < nchunk) load_stage(c2, c2 % NSTAGE);
        CP_COMMIT();

        const uint32_t stb = sbase + (uint32_t)sc * STAGE_BYTES;
        ldsm_step(stb, 0, 0);
        #pragma unroll
        for (int kk = 0; kk < 4; kk++) {
            const int cur = kk & 1;
            if (kk < 3) ldsm_step(stb, kk + 1, cur ^ 1);
            mma_step(cur);
        }
        if (++sc == NSTAGE) sc = 0;
    }

    #pragma unroll
    for (int mt = 0; mt < 4; mt++) {
        const int row = m0 + wm + mt * 16 + g;
        float iv0 = 1.f, iv8 = 1.f;
        if (!fexp && sums) {
            iv0 = __fdividef(1.f, sums[row]);
            iv8 = __fdividef(1.f, sums[row + 8]);
        }
        float s_lo = 0.f, s_hi = 0.f;
        #pragma unroll
        for (int nt = 0; nt < 4; nt++) {
            const int col = n0 + wn + nt * 8 + tg * 2;
            if (fexp) {
                // exp + causal intra-tile mask; store unnormalized half weights
                float e0 = (col     <= row)     ? __expf(acc[mt][nt][0]) : 0.f;
                float e1 = (col + 1 <= row)     ? __expf(acc[mt][nt][1]) : 0.f;
                float e2 = (col     <= row + 8) ? __expf(acc[mt][nt][2]) : 0.f;
                float e3 = (col + 1 <= row + 8) ? __expf(acc[mt][nt][3]) : 0.f;
                *(__half2*)(Ch_ + (size_t)row * N + col) = __floats2half2_rn(e0, e1);
                *(__half2*)(Ch_ + (size_t)(row + 8) * N + col) = __floats2half2_rn(e2, e3);
                s_lo += e0 + e1;
                s_hi += e2 + e3;
            } else if (out_half) {
                *(__half2*)(Ch_ + (size_t)row * N + col) =
                    __floats2half2_rn(acc[mt][nt][0] * osc, acc[mt][nt][1] * osc);
                *(__half2*)(Ch_ + (size_t)(row + 8) * N + col) =
                    __floats2half2_rn(acc[mt][nt][2] * osc, acc[mt][nt][3] * osc);
            } else {
                *(float2*)(Cf_ + (size_t)row * N + col) =
                    make_float2(acc[mt][nt][0] * iv0, acc[mt][nt][1] * iv0);
                *(float2*)(Cf_ + (size_t)(row + 8) * N + col) =
                    make_float2(acc[mt][nt][2] * iv8, acc[mt][nt][3] * iv8);
            }
        }
        if (fexp) {
            // quad reduce across tg lanes (lane = g*4 + tg)
            s_lo += __shfl_xor_sync(0xffffffffu, s_lo, 1);
            s_lo += __shfl_xor_sync(0xffffffffu, s_lo, 2);
            s_hi += __shfl_xor_sync(0xffffffffu, s_hi, 1);
            s_hi += __shfl_xor_sync(0xffffffffu, s_hi, 2);
            if (tg == 0) {
                atomicAdd(&sums[row], s_lo);
                atomicAdd(&sums[row + 8], s_hi);
            }
        }
    }
}

// ---------------- fp32 -> fp16 conversion, one launch ----------------
__global__ __launch_bounds__(256) void to_half_all(
    const float* __restrict__ x,  __half* __restrict__ xh,
    const float* __restrict__ w0, const float* __restrict__ w1, const float* __restrict__ w2,
    __half* __restrict__ wh)
{
    int i = blockIdx.x * 256 + threadIdx.x;
    const float* src;
    __half* dst;
    int off;
    if (i < NX4) { src = x; dst = xh; off = i; }
    else {
        int j = i - NX4;
        int w = j / NW4;
        off = j - w * NW4;
        src = (w == 0) ? w0 : (w == 1) ? w1 : w2;
        dst = wh + (size_t)w * (P_ * D_);
    }
    float4 v = ((const float4*)src)[off];
    __half2 h0 = __floats2half2_rn(v.x, v.y);
    __half2 h1 = __floats2half2_rn(v.z, v.w);
    ((uint2*)dst)[off] = make_uint2(*(uint32_t*)&h0, *(uint32_t*)&h1);
}

// ---------------- launcher (single stream) ----------------
extern "C" void kernel_launch(void* const* d_in, const int* in_sizes, int n_in,
                              void* d_out, int out_size)
{
    const float* x  = (const float*)d_in[0];
    const float* Wq = (const float*)d_in[1];
    const float* Wk = (const float*)d_in[2];
    const float* Wv = (const float*)d_in[3];
    float* out = (float*)d_out;

    __half *Q, *K, *V, *Wgt, *xh, *Wh;
    float *sum;
    cudaGetSymbolAddress((void**)&Q,   g_Q);
    cudaGetSymbolAddress((void**)&K,   g_K);
    cudaGetSymbolAddress((void**)&V,   g_V);
    cudaGetSymbolAddress((void**)&Wgt, g_W);
    cudaGetSymbolAddress((void**)&sum, g_sum);
    cudaGetSymbolAddress((void**)&xh,  g_xh);
    cudaGetSymbolAddress((void**)&Wh,  g_Wh);
    __half* Wqh = Wh;
    __half* Wkh = Wh + (size_t)P_ * D_;
    __half* Wvh = Wh + 2 * (size_t)P_ * D_;

    cudaFuncSetAttribute(gemm_nt_h, cudaFuncAttributeMaxDynamicSharedMemorySize, SMEM_BYTES);

    const int tot4 = NX4 + 3 * NW4;
    to_half_all<<<(tot4 + 255) / 256, 256>>>(x, xh, Wq, Wk, Wv, Wh);

    // zero row-sum accumulators (graph-capturable memset node)
    cudaMemsetAsync(sum, 0, (size_t)B_ * S_ * sizeof(float), 0);

    dim3 blk(NT_);

    // merged QKV projections; Q scaled by 1/sqrt(d) at the epilogue
    dim3 gproj(P_ / BN, (B_ * S_) / BM, 3);
    gemm_nt_h<<<gproj, blk, SMEM_BYTES>>>(xh, Wqh, Wkh, Wvh,
                                          nullptr, Q, K, V,
                                          B_ * S_, P_, D_, 0, 0, 0, 0, 0, 0, 1, 0,
                                          0.03125f, 0, nullptr);

    // exp-weights = exp((Q/32) @ K^T), causal mask, half out; row sums via atomics
    dim3 gsc(S_ / BN, S_ / BM, B_);
    gemm_nt_h<<<gsc, blk, SMEM_BYTES>>>(Q, K, nullptr, nullptr,
                                        nullptr, Wgt, nullptr, nullptr,
                                        S_, S_, P_,
                                        (long long)S_ * P_, (long long)S_ * P_,
                                        (long long)S_ * S_, 1, 1, 0, 1, 0, 1.f,
                                        1, sum);

    // Z = (expW @ V) / rowsum per batch (bt=1 trans path), k truncated
    dim3 gz(P_ / BN, S_ / BM, B_);
    gemm_nt_h<<<gz, blk, SMEM_BYTES>>>(Wgt, V, nullptr, nullptr,
                                       out, nullptr, nullptr, nullptr,
                                       S_, P_, S_,
                                       (long long)S_ * S_, (long long)S_ * P_,
                                       (long long)S_ * P_, 1, 0, 1, 0, 1, 1.f,
                                       0, sum);
}

// round 17
// speedup vs baseline: 1.0259x; 1.0024x over previous
#include <cuda_runtime.h>
#include <cuda_fp16.h>
#include <cstdint>

#define B_ 4
#define S_ 2048
#define D_ 1024
#define P_ 1024

#define BM 128
#define BN 128
#define BK 64                        // halves of k per chunk
#define NT_ 256
#define NSTAGE 3
#define BKH 72                       // A/B k-major row stride in halves (144B)
#define TILE_H (BM * BKH)
#define A_TILE_B (TILE_H * 2)        // 18432
#define STAGE_BYTES (2 * A_TILE_B)   // 36864
#define SMEM_BYTES (NSTAGE * STAGE_BYTES)  // 110592 -> 2 CTAs/SM

#define TPAD 136                     // transpose staging stride in halves (272B)

#define NX4 ((B_ * S_ * D_) / 4)
#define NW4 ((P_ * D_) / 4)

// Scratch (static device arrays; no dynamic allocation anywhere).
__device__ __half g_Q  [(size_t)B_ * S_ * P_];
__device__ __half g_K  [(size_t)B_ * S_ * P_];
__device__ __half g_Vt [(size_t)B_ * P_ * S_];   // V transposed: [b][p][s]
__device__ __half g_W  [(size_t)B_ * S_ * S_];   // unnormalized exp weights
__device__ float  g_sum[(size_t)B_ * S_];        // row sums (atomic-accumulated)
__device__ __half g_xh [(size_t)B_ * S_ * D_];
__device__ __half g_Wh [3][(size_t)P_ * D_];

__device__ __forceinline__ uint32_t smem_u32(const void* p) {
    uint32_t a;
    asm("{ .reg .u64 t; cvta.to.shared.u64 t, %1; cvt.u32.u64 %0, t; }" : "=r"(a) : "l"(p));
    return a;
}
__device__ __forceinline__ void cp16(uint32_t dst, const void* src) {
    asm volatile("cp.async.cg.shared.global [%0], [%1], 16;" :: "r"(dst), "l"(src));
}
#define CP_COMMIT() asm volatile("cp.async.commit_group;" ::: "memory")
#define CP_WAIT(n)  asm volatile("cp.async.wait_group %0;" :: "n"(n) : "memory")

#define LDSM4(r0, r1, r2, r3, a)                                                  \
    asm volatile("ldmatrix.sync.aligned.m8n8.x4.shared.b16 {%0,%1,%2,%3}, [%4];"  \
        : "=r"(r0), "=r"(r1), "=r"(r2), "=r"(r3) : "r"(a))

__device__ __forceinline__ void mma_f16(float* c, const uint32_t* a,
                                        uint32_t b0, uint32_t b1) {
    asm volatile(
        "mma.sync.aligned.m16n8k16.row.col.f32.f16.f16.f32 "
        "{%0,%1,%2,%3}, {%4,%5,%6,%7}, {%8,%9}, {%0,%1,%2,%3};"
        : "+f"(c[0]), "+f"(c[1]), "+f"(c[2]), "+f"(c[3])
        : "r"(a[0]), "r"(a[1]), "r"(a[2]), "r"(a[3]), "r"(b0), "r"(b1));
}

// C[m,n] = sum_k A[m,k] * B[n,k]; A,B half row-major k-major (non-trans LDSM).
// mode 0 (projections): z selects B0/B1/B2 -> Ch0/Ch1/Ch2 (half out);
//   z==0 (Q) scaled by ascale; z==2 (V) written TRANSPOSED to Ch2 as [b][p][s]
//   via smem staging (Ch2 = Vt base).
// mode 1: A += z*sA, B = B0 + z*sB, C = z-strided.
// fexp: epilogue stores exp(acc) with causal intra-tile mask (half out) and
//       atomically accumulates per-row sums into rsum[z*M + row].
// rinv mode (fexp==0, out_half==0, rsum!=null): scale row r by 1/rsum[z*M+r].
__global__ __launch_bounds__(NT_, 2) void gemm_nt_h(
    const __half* __restrict__ A,
    const __half* __restrict__ B0, const __half* __restrict__ B1, const __half* __restrict__ B2,
    float* __restrict__ Cf, __half* __restrict__ Ch0, __half* __restrict__ Ch1, __half* __restrict__ Ch2,
    int M, int N, int K, long long sA, long long sB, long long sC,
    int mode, int causal, int klim, int out_half, float ascale,
    int fexp, float* __restrict__ rsum)
{
    extern __shared__ char smraw[];
    const int m0 = blockIdx.y * BM;
    const int n0 = blockIdx.x * BN;
    if (causal && n0 > m0) return;

    const __half* B;
    float* Cf_ = Cf;
    __half* Ch_ = Ch0;
    float osc = 1.f;
    int vtile = 0;
    if (mode == 0) {
        B   = (blockIdx.z == 0) ? B0 : (blockIdx.z == 1) ? B1 : B2;
        Ch_ = (blockIdx.z == 0) ? Ch0 : (blockIdx.z == 1) ? Ch1 : Ch2;
        if (blockIdx.z == 0) osc = ascale;
        if (blockIdx.z == 2) vtile = 1;
    } else {
        A += (long long)blockIdx.z * sA;
        B = B0 + (long long)blockIdx.z * sB;
        if (out_half) Ch_ = Ch0 + (long long)blockIdx.z * sC;
        else          Cf_ = Cf  + (long long)blockIdx.z * sC;
    }
    float* sums = rsum ? (rsum + (long long)blockIdx.z * M) : nullptr;

    const int kmax = klim ? min(K, m0 + BM) : K;
    const int nchunk = kmax / BK;

    const int tid = threadIdx.x;
    const int wid = tid >> 5, lane = tid & 31;
    const int g = lane >> 2, tg = lane & 3;
    const int wm = (wid >> 2) * 64;
    const int wn = (wid & 3) * 32;

    const uint32_t sbase = smem_u32(smraw);
    const __half* Abase = A + (size_t)m0 * K;

    uint32_t offA[4], offB[2];
    {
        const int rA = lane & 15;
        const int cA = (lane >> 4) * 16;
        #pragma unroll
        for (int mt = 0; mt < 4; mt++)
            offA[mt] = (uint32_t)((wm + mt * 16 + rA) * BKH) * 2u + cA;
        const int rB = (lane & 7) + ((lane >> 4) << 3);
        const int cB = ((lane >> 3) & 1) * 16;
        #pragma unroll
        for (int gb = 0; gb < 2; gb++)
            offB[gb] = (uint32_t)A_TILE_B +
                       (uint32_t)((wn + gb * 16 + rB) * BKH) * 2u + cB;
    }

    float acc[4][4][4];
    #pragma unroll
    for (int i = 0; i < 4; i++)
        #pragma unroll
        for (int j = 0; j < 4; j++)
            #pragma unroll
            for (int r = 0; r < 4; r++) acc[i][j][r] = 0.f;

    auto load_stage = [&](int c, int s) {
        const uint32_t ab = sbase + (uint32_t)s * STAGE_BYTES;
        const uint32_t bb = ab + A_TILE_B;
        const __half* Ag = Abase + (size_t)c * BK;
        const __half* Bg = B + (size_t)n0 * K + (size_t)c * BK;
        #pragma unroll
        for (int j = 0; j < 4; j++) {
            int idx = j * NT_ + tid;
            int row = idx >> 3;
            int kc = (idx & 7) * 8;
            uint32_t doff = (uint32_t)(row * BKH + kc) * 2u;
            cp16(ab + doff, Ag + (size_t)row * K + kc);
            cp16(bb + doff, Bg + (size_t)row * K + kc);
        }
    };

    load_stage(0, 0);
    CP_COMMIT();
    load_stage(1, 1);
    CP_COMMIT();

    uint32_t af[2][4][4], bf[2][2][4];

    auto ldsm_step = [&](uint32_t stb, int kk, int buf) {
        const uint32_t ko = (uint32_t)kk * 32u;
        #pragma unroll
        for (int mt = 0; mt < 4; mt++)
            LDSM4(af[buf][mt][0], af[buf][mt][1], af[buf][mt][2], af[buf][mt][3],
                  stb + offA[mt] + ko);
        #pragma unroll
        for (int gb = 0; gb < 2; gb++)
            LDSM4(bf[buf][gb][0], bf[buf][gb][1], bf[buf][gb][2], bf[buf][gb][3],
                  stb + offB[gb] + ko);
    };
    auto mma_step = [&](int buf) {
        #pragma unroll
        for (int mt = 0; mt < 4; mt++)
            #pragma unroll
            for (int nt = 0; nt < 4; nt++)
                mma_f16(acc[mt][nt], af[buf][mt],
                        bf[buf][nt >> 1][(nt & 1) * 2], bf[buf][nt >> 1][(nt & 1) * 2 + 1]);
    };

    int sc = 0;
    for (int i = 0; i < nchunk; i++) {
        CP_WAIT(1);
        __syncthreads();

        const int c2 = i + 2;
        if (c2 < nchunk) load_stage(c2, c2 % NSTAGE);
        CP_COMMIT();

        const uint32_t stb = sbase + (uint32_t)sc * STAGE_BYTES;
        ldsm_step(stb, 0, 0);
        #pragma unroll
        for (int kk = 0; kk < 4; kk++) {
            const int cur = kk & 1;
            if (kk < 3) ldsm_step(stb, kk + 1, cur ^ 1);
            mma_step(cur);
        }
        if (++sc == NSTAGE) sc = 0;
    }

    if (vtile) {
        // ---- V tile: transpose via smem, write Vt[b][p][s] coalesced ----
        CP_WAIT(0);
        __syncthreads();                 // pipeline smem free for reuse
        __half* t = (__half*)smraw;      // [128 p][TPAD] staging
        #pragma unroll
        for (int mt = 0; mt < 4; mt++) {
            const int r0 = wm + mt * 16 + g;     // local s
            #pragma unroll
            for (int nt = 0; nt < 4; nt++) {
                const int c0 = wn + nt * 8 + tg * 2;   // local p
                t[(c0    ) * TPAD + r0    ] = __float2half_rn(acc[mt][nt][0]);
                t[(c0 + 1) * TPAD + r0    ] = __float2half_rn(acc[mt][nt][1]);
                t[(c0    ) * TPAD + r0 + 8] = __float2half_rn(acc[mt][nt][2]);
                t[(c0 + 1) * TPAD + r0 + 8] = __float2half_rn(acc[mt][nt][3]);
            }
        }
        __syncthreads();
        const int b = m0 >> 11;          // m0 / S_
        const int s0 = m0 & (S_ - 1);
        __half* Vtb = Ch_ + (size_t)b * P_ * S_;
        #pragma unroll
        for (int j = 0; j < 8; j++) {
            int v = j * NT_ + tid;       // 0..2047
            int pl = v >> 4;             // local p 0..127
            int sl = (v & 15) * 8;       // local s 0,8,...,120
            uint4 val = *(uint4*)(t + pl * TPAD + sl);
            *(uint4*)(Vtb + (size_t)(n0 + pl) * S_ + s0 + sl) = val;
        }
        return;
    }

    #pragma unroll
    for (int mt = 0; mt < 4; mt++) {
        const int row = m0 + wm + mt * 16 + g;
        float iv0 = 1.f, iv8 = 1.f;
        if (!fexp && sums) {
            iv0 = __fdividef(1.f, sums[row]);
            iv8 = __fdividef(1.f, sums[row + 8]);
        }
        float s_lo = 0.f, s_hi = 0.f;
        #pragma unroll
        for (int nt = 0; nt < 4; nt++) {
            const int col = n0 + wn + nt * 8 + tg * 2;
            if (fexp) {
                float e0 = (col     <= row)     ? __expf(acc[mt][nt][0]) : 0.f;
                float e1 = (col + 1 <= row)     ? __expf(acc[mt][nt][1]) : 0.f;
                float e2 = (col     <= row + 8) ? __expf(acc[mt][nt][2]) : 0.f;
                float e3 = (col + 1 <= row + 8) ? __expf(acc[mt][nt][3]) : 0.f;
                *(__half2*)(Ch_ + (size_t)row * N + col) = __floats2half2_rn(e0, e1);
                *(__half2*)(Ch_ + (size_t)(row + 8) * N + col) = __floats2half2_rn(e2, e3);
                s_lo += e0 + e1;
                s_hi += e2 + e3;
            } else if (out_half) {
                *(__half2*)(Ch_ + (size_t)row * N + col) =
                    __floats2half2_rn(acc[mt][nt][0] * osc, acc[mt][nt][1] * osc);
                *(__half2*)(Ch_ + (size_t)(row + 8) * N + col) =
                    __floats2half2_rn(acc[mt][nt][2] * osc, acc[mt][nt][3] * osc);
            } else {
                *(float2*)(Cf_ + (size_t)row * N + col) =
                    make_float2(acc[mt][nt][0] * iv0, acc[mt][nt][1] * iv0);
                *(float2*)(Cf_ + (size_t)(row + 8) * N + col) =
                    make_float2(acc[mt][nt][2] * iv8, acc[mt][nt][3] * iv8);
            }
        }
        if (fexp) {
            s_lo += __shfl_xor_sync(0xffffffffu, s_lo, 1);
            s_lo += __shfl_xor_sync(0xffffffffu, s_lo, 2);
            s_hi += __shfl_xor_sync(0xffffffffu, s_hi, 1);
            s_hi += __shfl_xor_sync(0xffffffffu, s_hi, 2);
            if (tg == 0) {
                atomicAdd(&sums[row], s_lo);
                atomicAdd(&sums[row + 8], s_hi);
            }
        }
    }
}

// ---------------- fp32 -> fp16 conversion, one launch ----------------
__global__ __launch_bounds__(256) void to_half_all(
    const float* __restrict__ x,  __half* __restrict__ xh,
    const float* __restrict__ w0, const float* __restrict__ w1, const float* __restrict__ w2,
    __half* __restrict__ wh)
{
    int i = blockIdx.x * 256 + threadIdx.x;
    const float* src;
    __half* dst;
    int off;
    if (i < NX4) { src = x; dst = xh; off = i; }
    else {
        int j = i - NX4;
        int w = j / NW4;
        off = j - w * NW4;
        src = (w == 0) ? w0 : (w == 1) ? w1 : w2;
        dst = wh + (size_t)w * (P_ * D_);
    }
    float4 v = ((const float4*)src)[off];
    __half2 h0 = __floats2half2_rn(v.x, v.y);
    __half2 h1 = __floats2half2_rn(v.z, v.w);
    ((uint2*)dst)[off] = make_uint2(*(uint32_t*)&h0, *(uint32_t*)&h1);
}

// ---------------- launcher (single stream) ----------------
extern "C" void kernel_launch(void* const* d_in, const int* in_sizes, int n_in,
                              void* d_out, int out_size)
{
    const float* x  = (const float*)d_in[0];
    const float* Wq = (const float*)d_in[1];
    const float* Wk = (const float*)d_in[2];
    const float* Wv = (const float*)d_in[3];
    float* out = (float*)d_out;

    __half *Q, *K, *Vt, *Wgt, *xh, *Wh;
    float *sum;
    cudaGetSymbolAddress((void**)&Q,   g_Q);
    cudaGetSymbolAddress((void**)&K,   g_K);
    cudaGetSymbolAddress((void**)&Vt,  g_Vt);
    cudaGetSymbolAddress((void**)&Wgt, g_W);
    cudaGetSymbolAddress((void**)&sum, g_sum);
    cudaGetSymbolAddress((void**)&xh,  g_xh);
    cudaGetSymbolAddress((void**)&Wh,  g_Wh);
    __half* Wqh = Wh;
    __half* Wkh = Wh + (size_t)P_ * D_;
    __half* Wvh = Wh + 2 * (size_t)P_ * D_;

    cudaFuncSetAttribute(gemm_nt_h, cudaFuncAttributeMaxDynamicSharedMemorySize, SMEM_BYTES);

    const int tot4 = NX4 + 3 * NW4;
    to_half_all<<<(tot4 + 255) / 256, 256>>>(x, xh, Wq, Wk, Wv, Wh);

    // zero row-sum accumulators (graph-capturable memset node)
    cudaMemsetAsync(sum, 0, (size_t)B_ * S_ * sizeof(float), 0);

    dim3 blk(NT_);

    // merged QKV projections; Q scaled by 1/sqrt(d); V written transposed
    dim3 gproj(P_ / BN, (B_ * S_) / BM, 3);
    gemm_nt_h<<<gproj, blk, SMEM_BYTES>>>(xh, Wqh, Wkh, Wvh,
                                          nullptr, Q, K, Vt,
                                          B_ * S_, P_, D_, 0, 0, 0, 0, 0, 0, 1,
                                          0.03125f, 0, nullptr);

    // exp-weights = exp((Q/32) @ K^T), causal mask, half out; row sums via atomics
    dim3 gsc(S_ / BN, S_ / BM, B_);
    gemm_nt_h<<<gsc, blk, SMEM_BYTES>>>(Q, K, nullptr, nullptr,
                                        nullptr, Wgt, nullptr, nullptr,
                                        S_, S_, P_,
                                        (long long)S_ * P_, (long long)S_ * P_,
                                        (long long)S_ * S_, 1, 1, 0, 1, 1.f,
                                        1, sum);

    // Z = (expW @ Vt^T) / rowsum per batch (non-trans path), k truncated
    dim3 gz(P_ / BN, S_ / BM, B_);
    gemm_nt_h<<<gz, blk, SMEM_BYTES>>>(Wgt, Vt, nullptr, nullptr,
                                       out, nullptr, nullptr, nullptr,
                                       S_, P_, S_,
                                       (long long)S_ * S_, (long long)P_ * S_,
                                       (long long)S_ * P_, 1, 0, 1, 0, 1.f,
                                       0, sum);
}